// round 1
// baseline (speedup 1.0000x reference)
#include <cuda_runtime.h>

#define N_POINTS 65536
#define N_GAUSS  1024
#define GSPLIT   2
#define GCHUNK   (N_GAUSS / GSPLIT)     // 512 gaussians per block's chunk
#define PPT      4                      // points per thread
#define BLOCK    256
#define PTILE    (BLOCK * PPT)          // 1024 points per block
#define NPT      (N_POINTS / PTILE)     // 64 point tiles

// Per-gaussian fused data: rows of M' = sqrt(0.5*log2(e)) * diag(1/s) * R,
// centers, alpha. 64 bytes = 4x float4 for LDS.128 broadcast.
struct __align__(16) Gauss {
    float4 a;   // m00 m01 m02 cx
    float4 b;   // m10 m11 m12 cy
    float4 c;   // m20 m21 m22 cz
    float4 d;   // alpha, pad, pad, pad
};

__device__ Gauss g_gauss[N_GAUSS];
__device__ float g_partial[GSPLIT][N_POINTS];

__global__ void precompute_kernel(const float* __restrict__ centers,
                                  const float* __restrict__ angles,
                                  const float* __restrict__ scales,
                                  const float* __restrict__ alphas) {
    int m = blockIdx.x * blockDim.x + threadIdx.x;
    if (m >= N_GAUSS) return;

    const float PI = 3.14159265358979323846f;
    // reference: rad = deg2rad(angles * 180) = angles * pi
    float ax = angles[3 * m + 0] * PI;
    float ay = angles[3 * m + 1] * PI;
    float az = angles[3 * m + 2] * PI;
    float sx, cx, sy, cy, sz, cz;
    sincosf(ax, &sx, &cx);
    sincosf(ay, &sy, &cy);
    sincosf(az, &sz, &cz);

    // R = Rz @ Ry @ Rx
    float r00 = cz * cy;
    float r01 = cz * sy * sx - sz * cx;
    float r02 = cz * sy * cx + sz * sx;
    float r10 = sz * cy;
    float r11 = sz * sy * sx + cz * cx;
    float r12 = sz * sy * cx - cz * sx;
    float r20 = -sy;
    float r21 = cy * sx;
    float r22 = cy * cx;

    // fold 1/scale per row and the base-2 constant sqrt(0.5*log2(e))
    const float K = 0.84934163f; // sqrt(0.5 * 1.4426950408889634)
    float i0 = K / scales[3 * m + 0];
    float i1 = K / scales[3 * m + 1];
    float i2 = K / scales[3 * m + 2];

    Gauss g;
    g.a = make_float4(r00 * i0, r01 * i0, r02 * i0, centers[3 * m + 0]);
    g.b = make_float4(r10 * i1, r11 * i1, r12 * i1, centers[3 * m + 1]);
    g.c = make_float4(r20 * i2, r21 * i2, r22 * i2, centers[3 * m + 2]);
    g.d = make_float4(alphas[m], 0.f, 0.f, 0.f);
    g_gauss[m] = g;
}

__global__ void __launch_bounds__(BLOCK) eval_kernel(const float* __restrict__ points) {
    __shared__ Gauss sg[GCHUNK];   // 32 KB

    int gbase = blockIdx.y * GCHUNK;
    const float4* src = reinterpret_cast<const float4*>(&g_gauss[gbase]);
    float4* dst = reinterpret_cast<float4*>(sg);
    for (int i = threadIdx.x; i < GCHUNK * 4; i += BLOCK) dst[i] = src[i];
    __syncthreads();

    int p0 = blockIdx.x * PTILE + threadIdx.x;

    float px[PPT], py[PPT], pz[PPT], acc[PPT];
#pragma unroll
    for (int k = 0; k < PPT; k++) {
        int idx = p0 + k * BLOCK;
        px[k] = points[3 * idx + 0];
        py[k] = points[3 * idx + 1];
        pz[k] = points[3 * idx + 2];
        acc[k] = 0.f;
    }

    for (int m = 0; m < GCHUNK; m++) {
        float4 A = sg[m].a;
        float4 B = sg[m].b;
        float4 C = sg[m].c;
        float4 D = sg[m].d;
#pragma unroll
        for (int k = 0; k < PPT; k++) {
            float dx = px[k] - A.w;
            float dy = py[k] - B.w;
            float dz = pz[k] - C.w;
            float t0 = fmaf(A.x, dx, fmaf(A.y, dy, A.z * dz));
            float t1 = fmaf(B.x, dx, fmaf(B.y, dy, B.z * dz));
            float t2 = fmaf(C.x, dx, fmaf(C.y, dy, C.z * dz));
            float e = -fmaf(t0, t0, fmaf(t1, t1, t2 * t2));
            float w;
            asm("ex2.approx.ftz.f32 %0, %1;" : "=f"(w) : "f"(e));
            acc[k] = fmaf(D.x, w, acc[k]);
        }
    }

#pragma unroll
    for (int k = 0; k < PPT; k++) {
        g_partial[blockIdx.y][p0 + k * BLOCK] = acc[k];
    }
}

__global__ void combine_kernel(float* __restrict__ out) {
    int i = blockIdx.x * blockDim.x + threadIdx.x;
    float s = 0.f;
#pragma unroll
    for (int g = 0; g < GSPLIT; g++) s += g_partial[g][i];
    out[i] = s * (1.0f / N_GAUSS);
}

extern "C" void kernel_launch(void* const* d_in, const int* in_sizes, int n_in,
                              void* d_out, int out_size) {
    const float* points  = (const float*)d_in[0];
    const float* centers = (const float*)d_in[1];
    const float* angles  = (const float*)d_in[2];
    const float* scales  = (const float*)d_in[3];
    const float* alphas  = (const float*)d_in[4];
    float* out = (float*)d_out;

    precompute_kernel<<<(N_GAUSS + 255) / 256, 256>>>(centers, angles, scales, alphas);

    dim3 grid(NPT, GSPLIT);
    eval_kernel<<<grid, BLOCK>>>(points);

    combine_kernel<<<N_POINTS / 256, 256>>>(out);
}

// round 2
// speedup vs baseline: 1.1316x; 1.1316x over previous
#include <cuda_runtime.h>

#define N_POINTS 65536
#define N_GAUSS  1024
#define GSPLIT   4
#define GCHUNK   (N_GAUSS / GSPLIT)     // 256 gaussians per block chunk
#define BLOCK    256
#define PAIRS    4                      // packed point-pairs per thread (8 points)
#define PTILE    (BLOCK * 2 * PAIRS)    // 2048 points per block
#define NPT      (N_POINTS / PTILE)     // 32 point tiles -> grid 32x4 = 128 blocks

typedef unsigned long long u64;

// Per-gaussian fused params, each value duplicated into both halves of an f32x2:
// [m00 m01 m02 k0 | m10 m11 m12 k1 | m20 m21 m22 k2 | alpha pad]
// where row i of M = sqrt(0.5*log2(e)) * (1/s_i) * R_row_i and k_i = -dot(M_row_i, c).
__device__ u64 g_gauss2[N_GAUSS][14];
__device__ float g_partial[GSPLIT][N_POINTS];

__device__ __forceinline__ u64 pack2(float lo, float hi) {
    u64 r; asm("mov.b64 %0, {%1, %2};" : "=l"(r) : "f"(lo), "f"(hi)); return r;
}
__device__ __forceinline__ void unpack2(u64 v, float& lo, float& hi) {
    asm("mov.b64 {%0, %1}, %2;" : "=f"(lo), "=f"(hi) : "l"(v));
}
__device__ __forceinline__ u64 fma2(u64 a, u64 b, u64 c) {
    u64 d; asm("fma.rn.f32x2 %0, %1, %2, %3;" : "=l"(d) : "l"(a), "l"(b), "l"(c)); return d;
}
__device__ __forceinline__ u64 mul2(u64 a, u64 b) {
    u64 d; asm("mul.rn.f32x2 %0, %1, %2;" : "=l"(d) : "l"(a), "l"(b)); return d;
}
// 2^(-q): sign-flip via integer XOR (LOP3, alu pipe) then MUFU.EX2
__device__ __forceinline__ float ex2neg(float q) {
    float r;
    float nq = __uint_as_float(__float_as_uint(q) ^ 0x80000000u);
    asm("ex2.approx.ftz.f32 %0, %1;" : "=f"(r) : "f"(nq));
    return r;
}

__global__ void precompute_kernel(const float* __restrict__ centers,
                                  const float* __restrict__ angles,
                                  const float* __restrict__ scales,
                                  const float* __restrict__ alphas) {
    int m = blockIdx.x * blockDim.x + threadIdx.x;
    if (m >= N_GAUSS) return;

    // reference: rad = deg2rad(angles * 180) = angles * pi  ->  sinpi/cospi
    float sx, cx, sy, cy, sz, cz;
    sincospif(angles[3 * m + 0], &sx, &cx);
    sincospif(angles[3 * m + 1], &sy, &cy);
    sincospif(angles[3 * m + 2], &sz, &cz);

    // R = Rz @ Ry @ Rx
    float r00 = cz * cy;
    float r01 = cz * sy * sx - sz * cx;
    float r02 = cz * sy * cx + sz * sx;
    float r10 = sz * cy;
    float r11 = sz * sy * sx + cz * cx;
    float r12 = sz * sy * cx - cz * sx;
    float r20 = -sy;
    float r21 = cy * sx;
    float r22 = cy * cx;

    const float K = 0.84934163f;  // sqrt(0.5 * log2(e))
    float i0 = K / scales[3 * m + 0];
    float i1 = K / scales[3 * m + 1];
    float i2 = K / scales[3 * m + 2];

    float m00 = r00 * i0, m01 = r01 * i0, m02 = r02 * i0;
    float m10 = r10 * i1, m11 = r11 * i1, m12 = r12 * i1;
    float m20 = r20 * i2, m21 = r21 * i2, m22 = r22 * i2;

    float cx0 = centers[3 * m + 0];
    float cy0 = centers[3 * m + 1];
    float cz0 = centers[3 * m + 2];
    float k0 = -fmaf(m00, cx0, fmaf(m01, cy0, m02 * cz0));
    float k1 = -fmaf(m10, cx0, fmaf(m11, cy0, m12 * cz0));
    float k2 = -fmaf(m20, cx0, fmaf(m21, cy0, m22 * cz0));
    float al = alphas[m];

    u64* g = g_gauss2[m];
    g[0]  = pack2(m00, m00); g[1]  = pack2(m01, m01); g[2]  = pack2(m02, m02); g[3]  = pack2(k0, k0);
    g[4]  = pack2(m10, m10); g[5]  = pack2(m11, m11); g[6]  = pack2(m12, m12); g[7]  = pack2(k1, k1);
    g[8]  = pack2(m20, m20); g[9]  = pack2(m21, m21); g[10] = pack2(m22, m22); g[11] = pack2(k2, k2);
    g[12] = pack2(al, al);   g[13] = pack2(0.f, 0.f);
}

__global__ void __launch_bounds__(BLOCK) eval_kernel(const float* __restrict__ points) {
    __shared__ __align__(16) u64 sg[GCHUNK][14];   // 28 KB, pre-duplicated f32x2 params

    {
        const ulonglong2* src = reinterpret_cast<const ulonglong2*>(g_gauss2[blockIdx.y * GCHUNK]);
        ulonglong2* dst = reinterpret_cast<ulonglong2*>(sg);
        for (int i = threadIdx.x; i < GCHUNK * 7; i += BLOCK) dst[i] = src[i];
    }
    __syncthreads();

    int base = blockIdx.x * PTILE + threadIdx.x * 2;

    u64 px2[PAIRS], py2[PAIRS], pz2[PAIRS], acc2[PAIRS];
#pragma unroll
    for (int j = 0; j < PAIRS; j++) {
        int idx = base + j * (BLOCK * 2);
        const float2* p = reinterpret_cast<const float2*>(points + 3 * idx);
        float2 f0 = p[0], f1 = p[1], f2 = p[2];   // x0 y0 | z0 x1 | y1 z1
        px2[j] = pack2(f0.x, f1.y);
        py2[j] = pack2(f0.y, f2.x);
        pz2[j] = pack2(f1.x, f2.y);
        acc2[j] = pack2(0.f, 0.f);
    }

#pragma unroll 1
    for (int m = 0; m < GCHUNK; m++) {
        const ulonglong2* gv = reinterpret_cast<const ulonglong2*>(sg[m]);
        ulonglong2 w0 = gv[0], w1 = gv[1], w2 = gv[2], w3 = gv[3],
                   w4 = gv[4], w5 = gv[5], w6 = gv[6];
        u64 m00 = w0.x, m01 = w0.y, m02 = w1.x, k0 = w1.y;
        u64 m10 = w2.x, m11 = w2.y, m12 = w3.x, k1 = w3.y;
        u64 m20 = w4.x, m21 = w4.y, m22 = w5.x, k2 = w5.y;
        u64 al  = w6.x;
#pragma unroll
        for (int j = 0; j < PAIRS; j++) {
            u64 t0 = fma2(m00, px2[j], fma2(m01, py2[j], fma2(m02, pz2[j], k0)));
            u64 t1 = fma2(m10, px2[j], fma2(m11, py2[j], fma2(m12, pz2[j], k1)));
            u64 t2 = fma2(m20, px2[j], fma2(m21, py2[j], fma2(m22, pz2[j], k2)));
            u64 q  = fma2(t0, t0, fma2(t1, t1, mul2(t2, t2)));
            float qlo, qhi; unpack2(q, qlo, qhi);
            u64 e2 = pack2(ex2neg(qlo), ex2neg(qhi));
            acc2[j] = fma2(al, e2, acc2[j]);
        }
    }

    float* part = g_partial[blockIdx.y];
#pragma unroll
    for (int j = 0; j < PAIRS; j++) {
        int idx = base + j * (BLOCK * 2);
        float lo, hi; unpack2(acc2[j], lo, hi);
        *reinterpret_cast<float2*>(part + idx) = make_float2(lo, hi);
    }
}

__global__ void combine_kernel(float* __restrict__ out) {
    int i = blockIdx.x * blockDim.x + threadIdx.x;
    float s = 0.f;
#pragma unroll
    for (int g = 0; g < GSPLIT; g++) s += g_partial[g][i];
    out[i] = s * (1.0f / N_GAUSS);
}

extern "C" void kernel_launch(void* const* d_in, const int* in_sizes, int n_in,
                              void* d_out, int out_size) {
    const float* points  = (const float*)d_in[0];
    const float* centers = (const float*)d_in[1];
    const float* angles  = (const float*)d_in[2];
    const float* scales  = (const float*)d_in[3];
    const float* alphas  = (const float*)d_in[4];
    float* out = (float*)d_out;

    precompute_kernel<<<(N_GAUSS + 255) / 256, 256>>>(centers, angles, scales, alphas);

    dim3 grid(NPT, GSPLIT);
    eval_kernel<<<grid, BLOCK>>>(points);

    combine_kernel<<<N_POINTS / 256, 256>>>(out);
}

// round 3
// speedup vs baseline: 1.4793x; 1.3073x over previous
#include <cuda_runtime.h>

#define N_POINTS 65536
#define N_GAUSS  1024
#define GSPLIT   4
#define GCHUNK   (N_GAUSS / GSPLIT)     // 256 gaussians per block chunk
#define BLOCK    256
#define PAIRS    4                      // packed point-pairs per thread (8 points)
#define PTILE    (BLOCK * 2 * PAIRS)    // 2048 points per block
#define NPT      (N_POINTS / PTILE)     // 32 point tiles -> grid 32x4 = 128 blocks

typedef unsigned long long u64;

// Per-gaussian fused params (each duplicated into both f32x2 halves):
// [l00 l10 l20 k0 | l11 l21 k1 | l22 k2 | nl2a]  (10 x u64 = 80B)
// where A = M^T M = L L^T (fp64 Cholesky), t = L^T p + k, k = -L^T c,
// weight = 2^(-(|t|^2 + nl2a)) with nl2a = -log2(alpha).
__device__ u64 g_gauss2[N_GAUSS][10];
__device__ float g_partial[GSPLIT][N_POINTS];

__device__ __forceinline__ u64 pack2(float lo, float hi) {
    u64 r; asm("mov.b64 %0, {%1, %2};" : "=l"(r) : "f"(lo), "f"(hi)); return r;
}
__device__ __forceinline__ void unpack2(u64 v, float& lo, float& hi) {
    asm("mov.b64 {%0, %1}, %2;" : "=f"(lo), "=f"(hi) : "l"(v));
}
__device__ __forceinline__ u64 fma2(u64 a, u64 b, u64 c) {
    u64 d; asm("fma.rn.f32x2 %0, %1, %2, %3;" : "=l"(d) : "l"(a), "l"(b), "l"(c)); return d;
}
__device__ __forceinline__ u64 add2(u64 a, u64 b) {
    u64 d; asm("add.rn.f32x2 %0, %1, %2;" : "=l"(d) : "l"(a), "l"(b)); return d;
}
__device__ __forceinline__ float ex2f(float e) {
    float r; asm("ex2.approx.ftz.f32 %0, %1;" : "=f"(r) : "f"(e)); return r;
}

// grid <<<32, 32>>> : one gaussian per thread, fp64 for conditioning.
__global__ void precompute_kernel(const float* __restrict__ centers,
                                  const float* __restrict__ angles,
                                  const float* __restrict__ scales,
                                  const float* __restrict__ alphas) {
    int m = blockIdx.x * blockDim.x + threadIdx.x;
    if (m >= N_GAUSS) return;

    // reference: rad = deg2rad(angles * 180) = angles * pi
    float sx, cx, sy, cy, sz, cz;
    sincospif(angles[3 * m + 0], &sx, &cx);
    sincospif(angles[3 * m + 1], &sy, &cy);
    sincospif(angles[3 * m + 2], &sz, &cz);

    // R = Rz @ Ry @ Rx
    double r00 = (double)cz * cy;
    double r01 = (double)cz * sy * sx - (double)sz * cx;
    double r02 = (double)cz * sy * cx + (double)sz * sx;
    double r10 = (double)sz * cy;
    double r11 = (double)sz * sy * sx + (double)cz * cx;
    double r12 = (double)sz * sy * cx - (double)cz * sx;
    double r20 = -(double)sy;
    double r21 = (double)cy * sx;
    double r22 = (double)cy * cx;

    const double K = 0.8493416216817514;  // sqrt(0.5 * log2(e))
    double i0 = K / (double)scales[3 * m + 0];
    double i1 = K / (double)scales[3 * m + 1];
    double i2 = K / (double)scales[3 * m + 2];

    // M = diag(i) R  (rows scaled)
    double m00 = r00 * i0, m01 = r01 * i0, m02 = r02 * i0;
    double m10 = r10 * i1, m11 = r11 * i1, m12 = r12 * i1;
    double m20 = r20 * i2, m21 = r21 * i2, m22 = r22 * i2;

    // A = M^T M (symmetric, columns dot columns)
    double a00 = m00 * m00 + m10 * m10 + m20 * m20;
    double a01 = m00 * m01 + m10 * m11 + m20 * m21;
    double a02 = m00 * m02 + m10 * m12 + m20 * m22;
    double a11 = m01 * m01 + m11 * m11 + m21 * m21;
    double a12 = m01 * m02 + m11 * m12 + m21 * m22;
    double a22 = m02 * m02 + m12 * m12 + m22 * m22;

    // Cholesky A = L L^T (lower). q = |L^T d|^2.
    double l00 = sqrt(a00);
    double l10 = a01 / l00;
    double l20 = a02 / l00;
    double l11 = sqrt(a11 - l10 * l10);
    double l21 = (a12 - l10 * l20) / l11;
    double l22 = sqrt(a22 - l20 * l20 - l21 * l21);

    double c0 = centers[3 * m + 0];
    double c1 = centers[3 * m + 1];
    double c2 = centers[3 * m + 2];
    // t0 = l00 x + l10 y + l20 z + k0 ; t1 = l11 y + l21 z + k1 ; t2 = l22 z + k2
    double k0 = -(l00 * c0 + l10 * c1 + l20 * c2);
    double k1 = -(l11 * c1 + l21 * c2);
    double k2 = -(l22 * c2);

    float al = alphas[m];
    float nl2a = -log2f(al);   // al==0 -> +inf -> weight exactly 0 (correct)

    u64* g = g_gauss2[m];
    float f;
    f = (float)l00;  g[0] = pack2(f, f);
    f = (float)l10;  g[1] = pack2(f, f);
    f = (float)l20;  g[2] = pack2(f, f);
    f = (float)k0;   g[3] = pack2(f, f);
    f = (float)l11;  g[4] = pack2(f, f);
    f = (float)l21;  g[5] = pack2(f, f);
    f = (float)k1;   g[6] = pack2(f, f);
    f = (float)l22;  g[7] = pack2(f, f);
    f = (float)k2;   g[8] = pack2(f, f);
    g[9] = pack2(nl2a, nl2a);
}

__global__ void __launch_bounds__(BLOCK) eval_kernel(const float* __restrict__ points) {
    __shared__ __align__(16) u64 sg[GCHUNK][10];   // 20 KB

    {
        const ulonglong2* src = reinterpret_cast<const ulonglong2*>(g_gauss2[blockIdx.y * GCHUNK]);
        ulonglong2* dst = reinterpret_cast<ulonglong2*>(sg);
        for (int i = threadIdx.x; i < GCHUNK * 5; i += BLOCK) dst[i] = src[i];
    }
    __syncthreads();

    int base = blockIdx.x * PTILE + threadIdx.x * 2;

    u64 px2[PAIRS], py2[PAIRS], pz2[PAIRS], acc2[PAIRS];
#pragma unroll
    for (int j = 0; j < PAIRS; j++) {
        int idx = base + j * (BLOCK * 2);
        const float2* p = reinterpret_cast<const float2*>(points + 3 * idx);
        float2 f0 = p[0], f1 = p[1], f2 = p[2];   // x0 y0 | z0 x1 | y1 z1
        px2[j] = pack2(f0.x, f1.y);
        py2[j] = pack2(f0.y, f2.x);
        pz2[j] = pack2(f1.x, f2.y);
        acc2[j] = pack2(0.f, 0.f);
    }

#pragma unroll 2
    for (int m = 0; m < GCHUNK; m++) {
        const ulonglong2* gv = reinterpret_cast<const ulonglong2*>(sg[m]);
        ulonglong2 w0 = gv[0], w1 = gv[1], w2 = gv[2], w3 = gv[3], w4 = gv[4];
        u64 l00 = w0.x, l10 = w0.y, l20 = w1.x, k0 = w1.y;
        u64 l11 = w2.x, l21 = w2.y, k1 = w3.x;
        u64 l22 = w3.y, k2 = w4.x, nl2a = w4.y;
#pragma unroll
        for (int j = 0; j < PAIRS; j++) {
            u64 t0 = fma2(l00, px2[j], fma2(l10, py2[j], fma2(l20, pz2[j], k0)));
            u64 t1 = fma2(l11, py2[j], fma2(l21, pz2[j], k1));
            u64 t2 = fma2(l22, pz2[j], k2);
            u64 u  = fma2(t0, t0, fma2(t1, t1, fma2(t2, t2, nl2a)));
            u64 e  = u ^ 0x8000000080000000ull;       // negate both lanes (alu pipe)
            float elo, ehi; unpack2(e, elo, ehi);
            u64 w2x = pack2(ex2f(elo), ex2f(ehi));
            acc2[j] = add2(acc2[j], w2x);
        }
    }

    float* part = g_partial[blockIdx.y];
#pragma unroll
    for (int j = 0; j < PAIRS; j++) {
        int idx = base + j * (BLOCK * 2);
        float lo, hi; unpack2(acc2[j], lo, hi);
        *reinterpret_cast<float2*>(part + idx) = make_float2(lo, hi);
    }
}

__global__ void combine_kernel(float* __restrict__ out) {
    int i = blockIdx.x * blockDim.x + threadIdx.x;
    float s = 0.f;
#pragma unroll
    for (int g = 0; g < GSPLIT; g++) s += g_partial[g][i];
    out[i] = s * (1.0f / N_GAUSS);
}

extern "C" void kernel_launch(void* const* d_in, const int* in_sizes, int n_in,
                              void* d_out, int out_size) {
    const float* points  = (const float*)d_in[0];
    const float* centers = (const float*)d_in[1];
    const float* angles  = (const float*)d_in[2];
    const float* scales  = (const float*)d_in[3];
    const float* alphas  = (const float*)d_in[4];
    float* out = (float*)d_out;

    precompute_kernel<<<32, 32>>>(centers, angles, scales, alphas);

    dim3 grid(NPT, GSPLIT);
    eval_kernel<<<grid, BLOCK>>>(points);

    combine_kernel<<<N_POINTS / 256, 256>>>(out);
}